// round 1
// baseline (speedup 1.0000x reference)
#include <cuda_runtime.h>
#include <cuda_bf16.h>

// Problem constants (fixed by setup_inputs):
//   pc:      (64, 1, 64, 128) float32  -> 524288 elems
//   targets: (64, 512, 1024)  int32    -> 33554432 elems
// Mask depends only on targets[:64, :64, :]:
//   counts[i,j] = #(targets[8i..8i+8, 8j..8j+8, :] == 2), 65536 elems/cell
//   cond[i,j]   = (counts > 0) && (counts < 65536)
//   t[b,0,y,x]  = cond[y,x] if y<8 && x<8 else 0
//   loss = -mean( t*log(pc) + (1-t)*log1p(-pc) )

#define N_PC        524288      // 64*64*128
#define N_PC4       131072      // float4 count
#define NBLK_LOSS   256
#define NBLK_COUNT  512         // 8 blocks per cell (one batch each)
#define CELL_ELEMS  65536       // 8*8*1024

__device__ int   g_counts[64];
__device__ float g_partials[NBLK_LOSS];

__global__ void zero_counts_kernel() {
    if (threadIdx.x < 64) g_counts[threadIdx.x] = 0;
}

// Grid: 512 blocks. block = cell*8 + part. cell = i*8 + j.
// Each block handles batch b = 8i+part, H-rows [8j, 8j+8), full W=1024.
// That's 8 rows * 256 int4 = 2048 int4 = 256 thr * 8 loads.
__global__ void __launch_bounds__(256) count_kernel(const int* __restrict__ targets) {
    const int cell = blockIdx.x >> 3;
    const int part = blockIdx.x & 7;
    const int i = cell >> 3;
    const int j = cell & 7;
    const int b = i * 8 + part;

    // int4 base: b * (512*1024/4) + (8j) * (1024/4)
    const int4* __restrict__ base =
        reinterpret_cast<const int4*>(targets) + (size_t)b * 131072 + (size_t)j * 2048;

    const int tid = threadIdx.x;
    int cnt = 0;
#pragma unroll
    for (int k = 0; k < 8; k++) {
        int4 v = base[k * 256 + tid];
        cnt += (v.x == 2) + (v.y == 2) + (v.z == 2) + (v.w == 2);
    }
#pragma unroll
    for (int o = 16; o; o >>= 1) cnt += __shfl_down_sync(0xffffffffu, cnt, o);

    __shared__ int ws[8];
    if ((tid & 31) == 0) ws[tid >> 5] = cnt;
    __syncthreads();
    if (tid < 8) {
        cnt = ws[tid];
#pragma unroll
        for (int o = 4; o; o >>= 1) cnt += __shfl_down_sync(0xffu, cnt, o);
        if (tid == 0) atomicAdd(&g_counts[cell], cnt);
    }
}

// Grid: 256 blocks * 256 threads, 2 float4 per thread over 131072 float4.
// pc layout (b, y, x): elem e = b*8192 + y*128 + x.
// float4 index f: rem4 = f & 2047; y = rem4 >> 5; x4 = rem4 & 31.
// Special (mask-dependent) iff y<8 && x4<2.
__global__ void __launch_bounds__(256) loss_kernel(const float* __restrict__ pc) {
    const int tid = threadIdx.x;
    const int gid = blockIdx.x * 256 + tid;
    const float4* __restrict__ p4 = reinterpret_cast<const float4*>(pc);

    float acc = 0.0f;
#pragma unroll
    for (int it = 0; it < 2; it++) {
        const int f = it * 65536 + gid;
        const float4 v = p4[f];
        const int rem4 = f & 2047;
        const int y   = rem4 >> 5;
        const int x4  = rem4 & 31;
        if (y < 8 && x4 < 2) {
            const float pv[4] = {v.x, v.y, v.z, v.w};
#pragma unroll
            for (int l = 0; l < 4; l++) {
                const int x = x4 * 4 + l;
                const int c = g_counts[y * 8 + x];
                const bool t = (c > 0) && (c < CELL_ELEMS);
                acc += t ? logf(pv[l]) : log1pf(-pv[l]);
            }
        } else {
            acc += log1pf(-v.x) + log1pf(-v.y) + log1pf(-v.z) + log1pf(-v.w);
        }
    }

#pragma unroll
    for (int o = 16; o; o >>= 1) acc += __shfl_down_sync(0xffffffffu, acc, o);

    __shared__ float ws[8];
    if ((tid & 31) == 0) ws[tid >> 5] = acc;
    __syncthreads();
    if (tid < 8) {
        acc = ws[tid];
#pragma unroll
        for (int o = 4; o; o >>= 1) acc += __shfl_down_sync(0xffu, acc, o);
        if (tid == 0) g_partials[blockIdx.x] = acc;
    }
}

__global__ void __launch_bounds__(256) final_kernel(float* __restrict__ out) {
    const int tid = threadIdx.x;
    float acc = g_partials[tid];
#pragma unroll
    for (int o = 16; o; o >>= 1) acc += __shfl_down_sync(0xffffffffu, acc, o);

    __shared__ float ws[8];
    if ((tid & 31) == 0) ws[tid >> 5] = acc;
    __syncthreads();
    if (tid < 8) {
        acc = ws[tid];
#pragma unroll
        for (int o = 4; o; o >>= 1) acc += __shfl_down_sync(0xffu, acc, o);
        if (tid == 0) *out = -acc * (1.0f / (float)N_PC);
    }
}

extern "C" void kernel_launch(void* const* d_in, const int* in_sizes, int n_in,
                              void* d_out, int out_size) {
    // Identify inputs by size (pc = 524288 elems, targets = 33554432 elems).
    const float* pc;
    const int*   targets;
    if (in_sizes[0] == N_PC) {
        pc      = (const float*)d_in[0];
        targets = (const int*)d_in[1];
    } else {
        pc      = (const float*)d_in[1];
        targets = (const int*)d_in[0];
    }
    float* out = (float*)d_out;

    zero_counts_kernel<<<1, 64>>>();
    count_kernel<<<NBLK_COUNT, 256>>>(targets);
    loss_kernel<<<NBLK_LOSS, 256>>>(pc);
    final_kernel<<<1, 256>>>(out);
}